// round 6
// baseline (speedup 1.0000x reference)
#include <cuda_runtime.h>

#define NB   64
#define NS   512
#define NE   300
#define NH   256
#define NG   1024
#define NT   48
#define NH2  512
#define NTOK (NB*NS)

__device__ float g_z[(size_t)2 * NTOK * NG];
__device__ float g_hout[(size_t)NTOK * NH2];
__device__ float g_probs[(size_t)NTOK * NT];
__device__ float g_hcur[2 * 2 * NB * NH];
__device__ int   g_bar[16];
__device__ float g_res[NB];

__device__ __forceinline__ float fast_sig(float x) { return 1.f / (1.f + __expf(-x)); }
__device__ __forceinline__ float fast_tanh(float x) { return 2.f / (1.f + __expf(-2.f * x)) - 1.f; }

__global__ void init_bar_kernel() {
    if (threadIdx.x < 16) g_bar[threadIdx.x] = 0;
}

// =====================================================================
// K1: embedding gather + input projection GEMM
// 128x64 tile, 8x4 microtile, K = 5 chunks of 60.
// =====================================================================
__global__ void __launch_bounds__(256) input_gemm_kernel(
    const int* __restrict__ tok, const float* __restrict__ emb,
    const float* __restrict__ wf, const float* __restrict__ wb,
    const float* __restrict__ bif, const float* __restrict__ bhf,
    const float* __restrict__ bib, const float* __restrict__ bhb)
{
    __shared__ float As[60 * 132];   // [k][token] pad 132
    __shared__ float Bs[60 * 68];    // [k][gate]  pad 68
    __shared__ int   ids[128];

    int tid = threadIdx.x;
    int tm = blockIdx.x;            // 256 tiles of 128 tokens
    int tn = blockIdx.y;            // 32 tiles of 64 gates
    int dir = tn >> 4;
    int rbase = (tn & 15) << 6;
    const float* __restrict__ W = dir ? wb : wf;

    if (tid < 128) ids[tid] = tok[tm * 128 + tid];

    float acc[8][4] = {};
    int tx = tid & 15, ty = tid >> 4;

    for (int kc = 0; kc < 5; ++kc) {
        int k0 = kc * 60;
        __syncthreads();
#pragma unroll
        for (int l = 0; l < 30; ++l) {
            int idx = tid + l * 256;          // 0..7679
            int i = idx / 60;
            int k = idx - i * 60;
            As[k * 132 + i] = emb[(size_t)ids[i] * NE + k0 + k];
        }
#pragma unroll
        for (int l = 0; l < 15; ++l) {
            int idx = tid + l * 256;          // 0..3839
            int i = idx / 60;
            int k = idx - i * 60;
            Bs[k * 68 + i] = W[(size_t)(rbase + i) * NE + k0 + k];
        }
        __syncthreads();
#pragma unroll 4
        for (int k = 0; k < 60; ++k) {
            float4 a0 = *(const float4*)(As + k * 132 + ty * 8);
            float4 a1 = *(const float4*)(As + k * 132 + ty * 8 + 4);
            float4 b4 = *(const float4*)(Bs + k * 68 + tx * 4);
            float av[8] = {a0.x, a0.y, a0.z, a0.w, a1.x, a1.y, a1.z, a1.w};
            float bv[4] = {b4.x, b4.y, b4.z, b4.w};
#pragma unroll
            for (int ii = 0; ii < 8; ++ii)
#pragma unroll
                for (int jj = 0; jj < 4; ++jj)
                    acc[ii][jj] = fmaf(av[ii], bv[jj], acc[ii][jj]);
        }
    }

    const float* bi = dir ? bib : bif;
    const float* bh = dir ? bhb : bhf;
    int gcol = rbase + tx * 4;
    float bx = bi[gcol + 0] + bh[gcol + 0];
    float by = bi[gcol + 1] + bh[gcol + 1];
    float bz = bi[gcol + 2] + bh[gcol + 2];
    float bw = bi[gcol + 3] + bh[gcol + 3];

#pragma unroll
    for (int ii = 0; ii < 8; ++ii) {
        int n = tm * 128 + ty * 8 + ii;
        float4 v;
        v.x = acc[ii][0] + bx; v.y = acc[ii][1] + by;
        v.z = acc[ii][2] + bz; v.w = acc[ii][3] + bw;
        *(float4*)&g_z[((size_t)dir * NTOK + n) * NG + gcol] = v;
    }
}

// =====================================================================
// K2: persistent BiLSTM recurrence (128 CTAs) with z prefetch across the
// step barrier.
// =====================================================================
__global__ void __launch_bounds__(128) lstm_kernel(
    const float* __restrict__ whhf, const float* __restrict__ whhb)
{
    extern __shared__ float sm[];
    float* Ws = sm;            // 32768 floats
    float* hs = sm + 32768;    // 2048 floats

    int bid = blockIdx.x;
    int dir = bid >> 6;
    int bg  = (bid >> 3) & 7;
    int sl  = bid & 7;
    int us  = sl << 5;
    int tid = threadIdx.x;
    int w   = tid >> 5;
    int lane = tid & 31;
    const float* __restrict__ W = dir ? whhb : whhf;

    for (int idx = tid; idx < 32768; idx += 128) {
        int r = idx & 127, k = idx >> 7;
        Ws[idx] = W[(size_t)((r & 3) * NH + us + (r >> 2)) * NH + k];
    }
    for (int i = tid; i < 2048; i += 128) hs[i] = 0.f;
    __syncthreads();

    int b0 = bg * 8 + w * 2, b1 = b0 + 1;
    int u = us + lane;
    int bar = dir * 8 + bg;
    const float* h0p = hs + (w * 2) * NH;
    const float* h1p = h0p + NH;
    const float4* wp = ((const float4*)Ws) + lane;
    volatile int* vb = (volatile int*)g_bar;
    float c0 = 0.f, c1 = 0.f;

    // preload z for t = 0
    int to0 = dir ? (NS - 1) : 0;
    size_t z0 = ((size_t)dir * NTOK + (size_t)b0 * NS + to0) * NG + u;
    size_t z1 = ((size_t)dir * NTOK + (size_t)b1 * NS + to0) * NG + u;
    float zi0 = g_z[z0], zf0 = g_z[z0 + 256], zg0 = g_z[z0 + 512], zo0 = g_z[z0 + 768];
    float zi1 = g_z[z1], zf1 = g_z[z1 + 256], zg1 = g_z[z1 + 512], zo1 = g_z[z1 + 768];

    for (int t = 0; t < NS; ++t) {
        int to = dir ? (NS - 1 - t) : t;

        float a0 = 0.f, a1 = 0.f, a2 = 0.f, a3 = 0.f;
        float a4 = 0.f, a5 = 0.f, a6 = 0.f, a7 = 0.f;
#pragma unroll 8
        for (int k = 0; k < NH; ++k) {
            float4 w4 = wp[k * 32];
            float h0 = h0p[k], h1 = h1p[k];
            a0 = fmaf(w4.x, h0, a0); a1 = fmaf(w4.y, h0, a1);
            a2 = fmaf(w4.z, h0, a2); a3 = fmaf(w4.w, h0, a3);
            a4 = fmaf(w4.x, h1, a4); a5 = fmaf(w4.y, h1, a5);
            a6 = fmaf(w4.z, h1, a6); a7 = fmaf(w4.w, h1, a7);
        }

        float i0 = fast_sig(zi0 + a0), f0 = fast_sig(zf0 + a1);
        float gg0 = fast_tanh(zg0 + a2), o0 = fast_sig(zo0 + a3);
        c0 = f0 * c0 + i0 * gg0;
        float hn0 = o0 * fast_tanh(c0);
        float i1 = fast_sig(zi1 + a4), f1 = fast_sig(zf1 + a5);
        float gg1 = fast_tanh(zg1 + a6), o1 = fast_sig(zo1 + a7);
        c1 = f1 * c1 + i1 * gg1;
        float hn1 = o1 * fast_tanh(c1);

        int wbuf = t & 1;
        g_hcur[((wbuf * 2 + dir) * NB + b0) * NH + u] = hn0;
        g_hcur[((wbuf * 2 + dir) * NB + b1) * NH + u] = hn1;
        g_hout[((size_t)b0 * NS + to) * NH2 + dir * NH + u] = hn0;
        g_hout[((size_t)b1 * NS + to) * NH2 + dir * NH + u] = hn1;

        // prefetch next step's z (independent of the barrier)
        float nzi0 = 0.f, nzf0 = 0.f, nzg0 = 0.f, nzo0 = 0.f;
        float nzi1 = 0.f, nzf1 = 0.f, nzg1 = 0.f, nzo1 = 0.f;
        if (t < NS - 1) {
            int to2 = dir ? (NS - 2 - t) : (t + 1);
            size_t n0 = ((size_t)dir * NTOK + (size_t)b0 * NS + to2) * NG + u;
            size_t n1 = ((size_t)dir * NTOK + (size_t)b1 * NS + to2) * NG + u;
            nzi0 = g_z[n0]; nzf0 = g_z[n0 + 256]; nzg0 = g_z[n0 + 512]; nzo0 = g_z[n0 + 768];
            nzi1 = g_z[n1]; nzf1 = g_z[n1 + 256]; nzg1 = g_z[n1 + 512]; nzo1 = g_z[n1 + 768];
        }

        __threadfence();
        __syncthreads();
        if (tid == 0) {
            atomicAdd(&g_bar[bar], 1);
            int tgt = 8 * (t + 1);
            while (vb[bar] < tgt) { }
        }
        __syncthreads();

        if (t < NS - 1) {
            for (int i = tid; i < 2048; i += 128) {
                hs[i] = __ldcg(&g_hcur[((wbuf * 2 + dir) * NB + bg * 8 + (i >> 8)) * NH + (i & 255)]);
            }
            __syncthreads();
        }

        zi0 = nzi0; zf0 = nzf0; zg0 = nzg0; zo0 = nzo0;
        zi1 = nzi1; zf1 = nzf1; zg1 = nzg1; zo1 = nzo1;
    }
}

// =====================================================================
// K3: logits + softmax, float4-vectorized (4 LDS.128 per 12 FFMA)
// =====================================================================
__global__ void __launch_bounds__(256) logits_kernel(
    const float* __restrict__ wlin, const float* __restrict__ blin)
{
    extern __shared__ float sm[];
    float* ws  = sm;             // 48 * 516
    float* hsm = sm + 24768;     // 16 * 512
    int tid = threadIdx.x;
    size_t n0 = (size_t)blockIdx.x * 16;

    for (int i = tid; i < NT * NH2; i += 256) ws[(i >> 9) * 516 + (i & 511)] = wlin[i];
    for (int i = tid; i < 16 * NH2; i += 256) hsm[i] = g_hout[n0 * NH2 + i];
    __syncthreads();

    int tk = tid >> 4, js = tid & 15;
    const float4* hp = (const float4*)(hsm + tk * NH2);
    const float4* w0 = (const float4*)(ws + (js * 3 + 0) * 516);
    const float4* w1 = (const float4*)(ws + (js * 3 + 1) * 516);
    const float4* w2 = (const float4*)(ws + (js * 3 + 2) * 516);
    float a0 = 0.f, a1 = 0.f, a2 = 0.f;
#pragma unroll 4
    for (int kk = 0; kk < 128; ++kk) {
        float4 h  = hp[kk];
        float4 x0 = w0[kk];
        float4 x1 = w1[kk];
        float4 x2 = w2[kk];
        a0 = fmaf(x0.x, h.x, a0); a0 = fmaf(x0.y, h.y, a0);
        a0 = fmaf(x0.z, h.z, a0); a0 = fmaf(x0.w, h.w, a0);
        a1 = fmaf(x1.x, h.x, a1); a1 = fmaf(x1.y, h.y, a1);
        a1 = fmaf(x1.z, h.z, a1); a1 = fmaf(x1.w, h.w, a1);
        a2 = fmaf(x2.x, h.x, a2); a2 = fmaf(x2.y, h.y, a2);
        a2 = fmaf(x2.z, h.z, a2); a2 = fmaf(x2.w, h.w, a2);
    }
    a0 += blin[js * 3 + 0]; a1 += blin[js * 3 + 1]; a2 += blin[js * 3 + 2];

    float m = fmaxf(a0, fmaxf(a1, a2));
#pragma unroll
    for (int off = 8; off; off >>= 1) m = fmaxf(m, __shfl_xor_sync(0xffffffffu, m, off, 16));
    float e0 = __expf(a0 - m), e1 = __expf(a1 - m), e2 = __expf(a2 - m);
    float s = e0 + e1 + e2;
#pragma unroll
    for (int off = 8; off; off >>= 1) s += __shfl_xor_sync(0xffffffffu, s, off, 16);
    float inv = 1.f / s;
    size_t pb = (n0 + tk) * NT + js * 3;
    g_probs[pb + 0] = e0 * inv;
    g_probs[pb + 1] = e1 * inv;
    g_probs[pb + 2] = e2 * inv;
}

// =====================================================================
// K4: CRF per batch element
// =====================================================================
__global__ void __launch_bounds__(64) crf_kernel(
    const int* __restrict__ labels, const int* __restrict__ seql,
    const float* __restrict__ trans, const float* __restrict__ st,
    const float* __restrict__ et)
{
    __shared__ float tr[NT * NT];
    __shared__ float alpha[NT];
    __shared__ float red[64];
    int b = blockIdx.x, tid = threadIdx.x;

    for (int i = tid; i < NT * NT; i += 64) tr[i] = trans[i];
    int L = seql[b];
    if (tid < NT) alpha[tid] = st[tid] + g_probs[(size_t)b * NS * NT + tid];
    __syncthreads();

    for (int t = 1; t < NS; ++t) {
        float na = 0.f;
        if (tid < NT) {
            float em = g_probs[((size_t)b * NS + t) * NT + tid];
            float m = -1e30f;
#pragma unroll 4
            for (int i = 0; i < NT; ++i) m = fmaxf(m, alpha[i] + tr[i * NT + tid]);
            float s = 0.f;
#pragma unroll 4
            for (int i = 0; i < NT; ++i) s += __expf(alpha[i] + tr[i * NT + tid] - m);
            na = m + __logf(s) + em;
        }
        __syncthreads();
        if (tid < NT && t < L) alpha[tid] = na;
        __syncthreads();
    }

    float loc = 0.f;
    const int* lb = labels + b * NS;
    for (int t = tid; t < NS; t += 64) {
        int tg = lb[t];
        if (t < L) {
            loc += g_probs[((size_t)b * NS + t) * NT + tg];
            if (t >= 1) loc += tr[lb[t - 1] * NT + tg];
        }
    }
    red[tid] = loc;
    __syncthreads();
    if (tid == 0) {
        float score = 0.f;
        for (int i = 0; i < 64; ++i) score += red[i];
        score += st[lb[0]] + et[lb[L - 1]];
        float m = -1e30f;
        for (int j = 0; j < NT; ++j) m = fmaxf(m, alpha[j] + et[j]);
        float s = 0.f;
        for (int j = 0; j < NT; ++j) s += __expf(alpha[j] + et[j] - m);
        float logz = m + __logf(s);
        g_res[b] = score - logz;
    }
}

__global__ void final_kernel(float* __restrict__ out) {
    if (threadIdx.x == 0) {
        float s = 0.f;
        for (int b = 0; b < NB; ++b) s += g_res[b];
        out[0] = -s;
    }
}

extern "C" void kernel_launch(void* const* d_in, const int* in_sizes, int n_in,
                              void* d_out, int out_size)
{
    (void)in_sizes; (void)n_in; (void)out_size;
    const int*   tok    = (const int*)d_in[0];
    const int*   seql   = (const int*)d_in[1];
    const int*   labels = (const int*)d_in[2];
    const float* emb    = (const float*)d_in[3];
    const float* wihf   = (const float*)d_in[4];
    const float* whhf   = (const float*)d_in[5];
    const float* bihf   = (const float*)d_in[6];
    const float* bhhf   = (const float*)d_in[7];
    const float* wihb   = (const float*)d_in[8];
    const float* whhb   = (const float*)d_in[9];
    const float* bihb   = (const float*)d_in[10];
    const float* bhhb   = (const float*)d_in[11];
    const float* wlin   = (const float*)d_in[12];
    const float* blin   = (const float*)d_in[13];
    const float* trans  = (const float*)d_in[14];
    const float* st     = (const float*)d_in[15];
    const float* et     = (const float*)d_in[16];
    float* out = (float*)d_out;

    cudaFuncSetAttribute(lstm_kernel,   cudaFuncAttributeMaxDynamicSharedMemorySize, 139264);
    cudaFuncSetAttribute(logits_kernel, cudaFuncAttributeMaxDynamicSharedMemorySize, 131840);

    dim3 g1(256, 32);
    input_gemm_kernel<<<g1, 256>>>(tok, emb, wihf, wihb, bihf, bhhf, bihb, bhhb);
    init_bar_kernel<<<1, 32>>>();
    lstm_kernel<<<128, 128, 139264>>>(whhf, whhb);
    logits_kernel<<<2048, 256, 131840>>>(wlin, blin);
    crf_kernel<<<64, 64>>>(labels, seql, trans, st, et);
    final_kernel<<<1, 32>>>(out);
}

// round 7
// speedup vs baseline: 1.2495x; 1.2495x over previous
#include <cuda_runtime.h>

#define NB   64
#define NS   512
#define NE   300
#define NH   256
#define NG   1024
#define NT   48
#define NH2  512
#define NTOK (NB*NS)

__device__ float g_z[(size_t)2 * NTOK * NG];
__device__ float g_hout[(size_t)NTOK * NH2];
__device__ float g_probs[(size_t)NTOK * NT];
__device__ float g_hcur[2 * 2 * NB * NH];
__device__ int   g_bar[16];
__device__ float g_res[NB];

__device__ __forceinline__ float fast_sig(float x) { return 1.f / (1.f + __expf(-x)); }
__device__ __forceinline__ float fast_tanh(float x) { return 2.f / (1.f + __expf(-2.f * x)) - 1.f; }

__global__ void init_bar_kernel() {
    if (threadIdx.x < 16) g_bar[threadIdx.x] = 0;
}

// =====================================================================
// K1: embedding gather + input projection GEMM (R5 version — measured good)
// 64x64 tile, 4x4 microtile, K = 5 chunks of 60.
// =====================================================================
__global__ void __launch_bounds__(256) input_gemm_kernel(
    const int* __restrict__ tok, const float* __restrict__ emb,
    const float* __restrict__ wf, const float* __restrict__ wb,
    const float* __restrict__ bif, const float* __restrict__ bhf,
    const float* __restrict__ bib, const float* __restrict__ bhb)
{
    __shared__ float As[60 * 68];
    __shared__ float Bs[60 * 68];
    __shared__ int   ids[64];

    int tid = threadIdx.x;
    int tm = blockIdx.x;
    int tn = blockIdx.y;
    int dir = tn >> 4;
    int rbase = (tn & 15) << 6;
    const float* __restrict__ W = dir ? wb : wf;

    if (tid < 64) ids[tid] = tok[tm * 64 + tid];

    float acc[4][4] = {{0.f}};
    int tx = tid & 15, ty = tid >> 4;

    for (int kc = 0; kc < 5; ++kc) {
        int k0 = kc * 60;
        __syncthreads();
#pragma unroll
        for (int l = 0; l < 15; ++l) {
            int idx = tid + l * 256;
            int i = idx / 60;
            int k = idx - i * 60;
            As[k * 68 + i] = emb[(size_t)ids[i] * NE + k0 + k];
            Bs[k * 68 + i] = W[(size_t)(rbase + i) * NE + k0 + k];
        }
        __syncthreads();
#pragma unroll 4
        for (int k = 0; k < 60; ++k) {
            float4 a4 = *(const float4*)(As + k * 68 + ty * 4);
            float4 b4 = *(const float4*)(Bs + k * 68 + tx * 4);
            float av[4] = {a4.x, a4.y, a4.z, a4.w};
            float bv[4] = {b4.x, b4.y, b4.z, b4.w};
#pragma unroll
            for (int ii = 0; ii < 4; ++ii)
#pragma unroll
                for (int jj = 0; jj < 4; ++jj)
                    acc[ii][jj] = fmaf(av[ii], bv[jj], acc[ii][jj]);
        }
    }

    const float* bi = dir ? bib : bif;
    const float* bh = dir ? bhb : bhf;
    int gcol = rbase + tx * 4;
    float bx = bi[gcol + 0] + bh[gcol + 0];
    float by = bi[gcol + 1] + bh[gcol + 1];
    float bz = bi[gcol + 2] + bh[gcol + 2];
    float bw = bi[gcol + 3] + bh[gcol + 3];

#pragma unroll
    for (int ii = 0; ii < 4; ++ii) {
        int n = tm * 64 + ty * 4 + ii;
        float4 v;
        v.x = acc[ii][0] + bx; v.y = acc[ii][1] + by;
        v.z = acc[ii][2] + bz; v.w = acc[ii][3] + bw;
        *(float4*)&g_z[((size_t)dir * NTOK + n) * NG + gcol] = v;
    }
}

// =====================================================================
// K2: persistent BiLSTM recurrence. 128 CTAs x 256 threads (8 warps =
// 2/SMSP for latency hiding). Thread (warp w, lane) handles batch
// bg*8+w, hidden unit us+lane. No cross-barrier prefetch (R6 suspect).
// =====================================================================
__global__ void __launch_bounds__(256) lstm_kernel(
    const float* __restrict__ whhf, const float* __restrict__ whhb)
{
    extern __shared__ float sm[];
    float* Ws = sm;            // 32768 floats: Ws[k*128 + u_local*4 + gate]
    float* hs = sm + 32768;    // 2048  floats: hs[b_local*256 + k]

    int bid = blockIdx.x;
    int dir = bid >> 6;
    int bg  = (bid >> 3) & 7;
    int sl  = bid & 7;
    int us  = sl << 5;
    int tid = threadIdx.x;
    int w   = tid >> 5;        // warp = batch within group (0..7)
    int lane = tid & 31;       // hidden unit within slice
    const float* __restrict__ W = dir ? whhb : whhf;

    for (int idx = tid; idx < 32768; idx += 256) {
        int r = idx & 127, k = idx >> 7;
        Ws[idx] = W[(size_t)((r & 3) * NH + us + (r >> 2)) * NH + k];
    }
    for (int i = tid; i < 2048; i += 256) hs[i] = 0.f;
    __syncthreads();

    int b = bg * 8 + w;
    int u = us + lane;
    int bar = dir * 8 + bg;
    const float* hp = hs + w * NH;
    const float4* wp = ((const float4*)Ws) + lane;
    volatile int* vb = (volatile int*)g_bar;
    float c = 0.f;

    for (int t = 0; t < NS; ++t) {
        int to = dir ? (NS - 1 - t) : t;
        size_t zb = ((size_t)dir * NTOK + (size_t)b * NS + to) * NG + u;
        float zi = g_z[zb], zf = g_z[zb + 256], zg = g_z[zb + 512], zo = g_z[zb + 768];

        float a0 = 0.f, a1 = 0.f, a2 = 0.f, a3 = 0.f;
#pragma unroll 8
        for (int k = 0; k < NH; ++k) {
            float4 w4 = wp[k * 32];
            float h = hp[k];
            a0 = fmaf(w4.x, h, a0); a1 = fmaf(w4.y, h, a1);
            a2 = fmaf(w4.z, h, a2); a3 = fmaf(w4.w, h, a3);
        }

        float ig = fast_sig(zi + a0), fg = fast_sig(zf + a1);
        float gg = fast_tanh(zg + a2), og = fast_sig(zo + a3);
        c = fg * c + ig * gg;
        float hn = og * fast_tanh(c);

        int wbuf = t & 1;
        g_hcur[((wbuf * 2 + dir) * NB + b) * NH + u] = hn;
        g_hout[((size_t)b * NS + to) * NH2 + dir * NH + u] = hn;

        __threadfence();
        __syncthreads();
        if (tid == 0) {
            atomicAdd(&g_bar[bar], 1);
            int tgt = 8 * (t + 1);
            while (vb[bar] < tgt) { }
        }
        __syncthreads();

        if (t < NS - 1) {
            for (int i = tid; i < 2048; i += 256) {
                hs[i] = __ldcg(&g_hcur[((wbuf * 2 + dir) * NB + bg * 8 + (i >> 8)) * NH + (i & 255)]);
            }
            __syncthreads();
        }
    }
}

// =====================================================================
// K3: logits + softmax (float4 version — measured neutral vs scalar)
// =====================================================================
__global__ void __launch_bounds__(256) logits_kernel(
    const float* __restrict__ wlin, const float* __restrict__ blin)
{
    extern __shared__ float sm[];
    float* ws  = sm;             // 48 * 516
    float* hsm = sm + 24768;     // 16 * 512
    int tid = threadIdx.x;
    size_t n0 = (size_t)blockIdx.x * 16;

    for (int i = tid; i < NT * NH2; i += 256) ws[(i >> 9) * 516 + (i & 511)] = wlin[i];
    for (int i = tid; i < 16 * NH2; i += 256) hsm[i] = g_hout[n0 * NH2 + i];
    __syncthreads();

    int tk = tid >> 4, js = tid & 15;
    const float4* hp = (const float4*)(hsm + tk * NH2);
    const float4* w0 = (const float4*)(ws + (js * 3 + 0) * 516);
    const float4* w1 = (const float4*)(ws + (js * 3 + 1) * 516);
    const float4* w2 = (const float4*)(ws + (js * 3 + 2) * 516);
    float a0 = 0.f, a1 = 0.f, a2 = 0.f;
#pragma unroll 4
    for (int kk = 0; kk < 128; ++kk) {
        float4 h  = hp[kk];
        float4 x0 = w0[kk];
        float4 x1 = w1[kk];
        float4 x2 = w2[kk];
        a0 = fmaf(x0.x, h.x, a0); a0 = fmaf(x0.y, h.y, a0);
        a0 = fmaf(x0.z, h.z, a0); a0 = fmaf(x0.w, h.w, a0);
        a1 = fmaf(x1.x, h.x, a1); a1 = fmaf(x1.y, h.y, a1);
        a1 = fmaf(x1.z, h.z, a1); a1 = fmaf(x1.w, h.w, a1);
        a2 = fmaf(x2.x, h.x, a2); a2 = fmaf(x2.y, h.y, a2);
        a2 = fmaf(x2.z, h.z, a2); a2 = fmaf(x2.w, h.w, a2);
    }
    a0 += blin[js * 3 + 0]; a1 += blin[js * 3 + 1]; a2 += blin[js * 3 + 2];

    float m = fmaxf(a0, fmaxf(a1, a2));
#pragma unroll
    for (int off = 8; off; off >>= 1) m = fmaxf(m, __shfl_xor_sync(0xffffffffu, m, off, 16));
    float e0 = __expf(a0 - m), e1 = __expf(a1 - m), e2 = __expf(a2 - m);
    float s = e0 + e1 + e2;
#pragma unroll
    for (int off = 8; off; off >>= 1) s += __shfl_xor_sync(0xffffffffu, s, off, 16);
    float inv = 1.f / s;
    size_t pb = (n0 + tk) * NT + js * 3;
    g_probs[pb + 0] = e0 * inv;
    g_probs[pb + 1] = e1 * inv;
    g_probs[pb + 2] = e2 * inv;
}

// =====================================================================
// K4: CRF per batch element
// =====================================================================
__global__ void __launch_bounds__(64) crf_kernel(
    const int* __restrict__ labels, const int* __restrict__ seql,
    const float* __restrict__ trans, const float* __restrict__ st,
    const float* __restrict__ et)
{
    __shared__ float tr[NT * NT];
    __shared__ float alpha[NT];
    __shared__ float red[64];
    int b = blockIdx.x, tid = threadIdx.x;

    for (int i = tid; i < NT * NT; i += 64) tr[i] = trans[i];
    int L = seql[b];
    if (tid < NT) alpha[tid] = st[tid] + g_probs[(size_t)b * NS * NT + tid];
    __syncthreads();

    for (int t = 1; t < NS; ++t) {
        float na = 0.f;
        if (tid < NT) {
            float em = g_probs[((size_t)b * NS + t) * NT + tid];
            float m = -1e30f;
#pragma unroll 4
            for (int i = 0; i < NT; ++i) m = fmaxf(m, alpha[i] + tr[i * NT + tid]);
            float s = 0.f;
#pragma unroll 4
            for (int i = 0; i < NT; ++i) s += __expf(alpha[i] + tr[i * NT + tid] - m);
            na = m + __logf(s) + em;
        }
        __syncthreads();
        if (tid < NT && t < L) alpha[tid] = na;
        __syncthreads();
    }

    float loc = 0.f;
    const int* lb = labels + b * NS;
    for (int t = tid; t < NS; t += 64) {
        int tg = lb[t];
        if (t < L) {
            loc += g_probs[((size_t)b * NS + t) * NT + tg];
            if (t >= 1) loc += tr[lb[t - 1] * NT + tg];
        }
    }
    red[tid] = loc;
    __syncthreads();
    if (tid == 0) {
        float score = 0.f;
        for (int i = 0; i < 64; ++i) score += red[i];
        score += st[lb[0]] + et[lb[L - 1]];
        float m = -1e30f;
        for (int j = 0; j < NT; ++j) m = fmaxf(m, alpha[j] + et[j]);
        float s = 0.f;
        for (int j = 0; j < NT; ++j) s += __expf(alpha[j] + et[j] - m);
        float logz = m + __logf(s);
        g_res[b] = score - logz;
    }
}

__global__ void final_kernel(float* __restrict__ out) {
    if (threadIdx.x == 0) {
        float s = 0.f;
        for (int b = 0; b < NB; ++b) s += g_res[b];
        out[0] = -s;
    }
}

extern "C" void kernel_launch(void* const* d_in, const int* in_sizes, int n_in,
                              void* d_out, int out_size)
{
    (void)in_sizes; (void)n_in; (void)out_size;
    const int*   tok    = (const int*)d_in[0];
    const int*   seql   = (const int*)d_in[1];
    const int*   labels = (const int*)d_in[2];
    const float* emb    = (const float*)d_in[3];
    const float* wihf   = (const float*)d_in[4];
    const float* whhf   = (const float*)d_in[5];
    const float* bihf   = (const float*)d_in[6];
    const float* bhhf   = (const float*)d_in[7];
    const float* wihb   = (const float*)d_in[8];
    const float* whhb   = (const float*)d_in[9];
    const float* bihb   = (const float*)d_in[10];
    const float* bhhb   = (const float*)d_in[11];
    const float* wlin   = (const float*)d_in[12];
    const float* blin   = (const float*)d_in[13];
    const float* trans  = (const float*)d_in[14];
    const float* st     = (const float*)d_in[15];
    const float* et     = (const float*)d_in[16];
    float* out = (float*)d_out;

    cudaFuncSetAttribute(lstm_kernel,   cudaFuncAttributeMaxDynamicSharedMemorySize, 139264);
    cudaFuncSetAttribute(logits_kernel, cudaFuncAttributeMaxDynamicSharedMemorySize, 131840);

    dim3 g1(512, 32);
    input_gemm_kernel<<<g1, 256>>>(tok, emb, wihf, wihb, bihf, bhhf, bihb, bhhb);
    init_bar_kernel<<<1, 32>>>();
    lstm_kernel<<<128, 256, 139264>>>(whhf, whhb);
    logits_kernel<<<2048, 256, 131840>>>(wlin, blin);
    crf_kernel<<<64, 64>>>(labels, seql, trans, st, et);
    final_kernel<<<1, 32>>>(out);
}

// round 8
// speedup vs baseline: 1.5288x; 1.2236x over previous
#include <cuda_runtime.h>

#define NB   64
#define NS   512
#define NE   300
#define NH   256
#define NG   1024
#define NT   48
#define NH2  512
#define NTOK (NB*NS)

__device__ float g_z[(size_t)2 * NTOK * NG];
__device__ float g_hout[(size_t)NTOK * NH2];
__device__ float g_probs[(size_t)NTOK * NT];
__device__ float g_hcur[2 * 2 * NB * NH];
__device__ int   g_bar[16];
__device__ float g_res[NB];

__device__ __forceinline__ float fast_sig(float x) { return 1.f / (1.f + __expf(-x)); }
__device__ __forceinline__ float fast_tanh(float x) { return 2.f / (1.f + __expf(-2.f * x)) - 1.f; }

__global__ void init_bar_kernel() {
    if (threadIdx.x < 16) g_bar[threadIdx.x] = 0;
}

// =====================================================================
// K1: embedding gather + input projection GEMM (unchanged, measured)
// =====================================================================
__global__ void __launch_bounds__(256) input_gemm_kernel(
    const int* __restrict__ tok, const float* __restrict__ emb,
    const float* __restrict__ wf, const float* __restrict__ wb,
    const float* __restrict__ bif, const float* __restrict__ bhf,
    const float* __restrict__ bib, const float* __restrict__ bhb)
{
    __shared__ float As[60 * 68];
    __shared__ float Bs[60 * 68];
    __shared__ int   ids[64];

    int tid = threadIdx.x;
    int tm = blockIdx.x;
    int tn = blockIdx.y;
    int dir = tn >> 4;
    int rbase = (tn & 15) << 6;
    const float* __restrict__ W = dir ? wb : wf;

    if (tid < 64) ids[tid] = tok[tm * 64 + tid];

    float acc[4][4] = {{0.f}};
    int tx = tid & 15, ty = tid >> 4;

    for (int kc = 0; kc < 5; ++kc) {
        int k0 = kc * 60;
        __syncthreads();
#pragma unroll
        for (int l = 0; l < 15; ++l) {
            int idx = tid + l * 256;
            int i = idx / 60;
            int k = idx - i * 60;
            As[k * 68 + i] = emb[(size_t)ids[i] * NE + k0 + k];
            Bs[k * 68 + i] = W[(size_t)(rbase + i) * NE + k0 + k];
        }
        __syncthreads();
#pragma unroll 4
        for (int k = 0; k < 60; ++k) {
            float4 a4 = *(const float4*)(As + k * 68 + ty * 4);
            float4 b4 = *(const float4*)(Bs + k * 68 + tx * 4);
            float av[4] = {a4.x, a4.y, a4.z, a4.w};
            float bv[4] = {b4.x, b4.y, b4.z, b4.w};
#pragma unroll
            for (int ii = 0; ii < 4; ++ii)
#pragma unroll
                for (int jj = 0; jj < 4; ++jj)
                    acc[ii][jj] = fmaf(av[ii], bv[jj], acc[ii][jj]);
        }
    }

    const float* bi = dir ? bib : bif;
    const float* bh = dir ? bhb : bhf;
    int gcol = rbase + tx * 4;
    float bx = bi[gcol + 0] + bh[gcol + 0];
    float by = bi[gcol + 1] + bh[gcol + 1];
    float bz = bi[gcol + 2] + bh[gcol + 2];
    float bw = bi[gcol + 3] + bh[gcol + 3];

#pragma unroll
    for (int ii = 0; ii < 4; ++ii) {
        int n = tm * 64 + ty * 4 + ii;
        float4 v;
        v.x = acc[ii][0] + bx; v.y = acc[ii][1] + by;
        v.z = acc[ii][2] + bz; v.w = acc[ii][3] + bw;
        *(float4*)&g_z[((size_t)dir * NTOK + n) * NG + gcol] = v;
    }
}

// =====================================================================
// K2: persistent BiLSTM recurrence, k-split warp specialization.
// 128 CTAs x 256 threads. CTA = (dir, batch-group of 8, 32-unit slice).
// Warp w owns k-range [32w, 32w+32): computes partial gate sums for all
// 8 batches (W read ONCE per SM per step), partials reduced via smem.
// Thread (tid>>5 = batch, lane = unit) owns c and does the activation.
// =====================================================================
__global__ void __launch_bounds__(256) lstm_kernel(
    const float* __restrict__ whhf, const float* __restrict__ whhb)
{
    extern __shared__ float sm[];
    float* Ws  = sm;             // 32768 floats: Ws[k*128 + unit*4 + gate]
    float* hs  = sm + 32768;     // 2048  floats: hs[b_local*256 + k]
    float* red = sm + 34816;     // 8192  floats: red[((kw*8+b)*32+u)*4+g]

    int bid = blockIdx.x;
    int dir = bid >> 6;
    int bg  = (bid >> 3) & 7;
    int sl  = bid & 7;
    int us  = sl << 5;
    int tid = threadIdx.x;
    int w   = tid >> 5;
    int lane = tid & 31;
    const float* __restrict__ W = dir ? whhb : whhf;

    for (int idx = tid; idx < 32768; idx += 256) {
        int r = idx & 127, k = idx >> 7;
        Ws[idx] = W[(size_t)((r & 3) * NH + us + (r >> 2)) * NH + k];
    }
    for (int i = tid; i < 2048; i += 256) hs[i] = 0.f;
    __syncthreads();

    int b = bg * 8 + w;            // batch this thread owns in phase 2
    int u = us + lane;             // hidden unit this thread owns
    int bar = dir * 8 + bg;
    int k0 = w * 32;               // k-range this warp owns in phase 1
    const float4* wp = ((const float4*)Ws) + lane;
    volatile int* vb = (volatile int*)g_bar;
    float c = 0.f;

    for (int t = 0; t < NS; ++t) {
        int to = dir ? (NS - 1 - t) : t;

        // ---- phase 1: partial GEMV over this warp's k-range, all 8 batches
        float acc0[8], acc1[8], acc2[8], acc3[8];
#pragma unroll
        for (int bb = 0; bb < 8; ++bb) { acc0[bb] = acc1[bb] = acc2[bb] = acc3[bb] = 0.f; }

#pragma unroll 4
        for (int kk = 0; kk < 32; ++kk) {
            int k = k0 + kk;
            float4 w4 = wp[k * 32];
#pragma unroll
            for (int bb = 0; bb < 8; ++bb) {
                float h = hs[bb * 256 + k];
                acc0[bb] = fmaf(w4.x, h, acc0[bb]);
                acc1[bb] = fmaf(w4.y, h, acc1[bb]);
                acc2[bb] = fmaf(w4.z, h, acc2[bb]);
                acc3[bb] = fmaf(w4.w, h, acc3[bb]);
            }
        }
#pragma unroll
        for (int bb = 0; bb < 8; ++bb) {
            float4 v; v.x = acc0[bb]; v.y = acc1[bb]; v.z = acc2[bb]; v.w = acc3[bb];
            *(float4*)&red[((w * 8 + bb) * 32 + lane) * 4] = v;
        }

        // hoist z-loads: overlap global latency with the reduction sync
        size_t zb = ((size_t)dir * NTOK + (size_t)b * NS + to) * NG + u;
        float zi = g_z[zb], zf = g_z[zb + 256], zg = g_z[zb + 512], zo = g_z[zb + 768];
        __syncthreads();

        // ---- phase 2: reduce 8 k-partials, activation, state update
        float a0 = zi, a1 = zf, a2 = zg, a3 = zo;
#pragma unroll
        for (int ww = 0; ww < 8; ++ww) {
            float4 p = *(const float4*)&red[((ww * 8 + w) * 32 + lane) * 4];
            a0 += p.x; a1 += p.y; a2 += p.z; a3 += p.w;
        }

        float ig = fast_sig(a0), fg = fast_sig(a1);
        float gg = fast_tanh(a2), og = fast_sig(a3);
        c = fg * c + ig * gg;
        float hn = og * fast_tanh(c);

        int wbuf = t & 1;
        g_hcur[((wbuf * 2 + dir) * NB + b) * NH + u] = hn;
        g_hout[((size_t)b * NS + to) * NH2 + dir * NH + u] = hn;

        __threadfence();
        __syncthreads();
        if (tid == 0) {
            atomicAdd(&g_bar[bar], 1);
            int tgt = 8 * (t + 1);
            while (vb[bar] < tgt) { }
        }
        __syncthreads();

        if (t < NS - 1) {
            for (int i = tid; i < 2048; i += 256) {
                hs[i] = __ldcg(&g_hcur[((wbuf * 2 + dir) * NB + bg * 8 + (i >> 8)) * NH + (i & 255)]);
            }
            __syncthreads();
        }
    }
}

// =====================================================================
// K3: logits + softmax (unchanged)
// =====================================================================
__global__ void __launch_bounds__(256) logits_kernel(
    const float* __restrict__ wlin, const float* __restrict__ blin)
{
    extern __shared__ float sm[];
    float* ws  = sm;             // 48 * 516
    float* hsm = sm + 24768;     // 16 * 512
    int tid = threadIdx.x;
    size_t n0 = (size_t)blockIdx.x * 16;

    for (int i = tid; i < NT * NH2; i += 256) ws[(i >> 9) * 516 + (i & 511)] = wlin[i];
    for (int i = tid; i < 16 * NH2; i += 256) hsm[i] = g_hout[n0 * NH2 + i];
    __syncthreads();

    int tk = tid >> 4, js = tid & 15;
    const float4* hp = (const float4*)(hsm + tk * NH2);
    const float4* w0 = (const float4*)(ws + (js * 3 + 0) * 516);
    const float4* w1 = (const float4*)(ws + (js * 3 + 1) * 516);
    const float4* w2 = (const float4*)(ws + (js * 3 + 2) * 516);
    float a0 = 0.f, a1 = 0.f, a2 = 0.f;
#pragma unroll 4
    for (int kk = 0; kk < 128; ++kk) {
        float4 h  = hp[kk];
        float4 x0 = w0[kk];
        float4 x1 = w1[kk];
        float4 x2 = w2[kk];
        a0 = fmaf(x0.x, h.x, a0); a0 = fmaf(x0.y, h.y, a0);
        a0 = fmaf(x0.z, h.z, a0); a0 = fmaf(x0.w, h.w, a0);
        a1 = fmaf(x1.x, h.x, a1); a1 = fmaf(x1.y, h.y, a1);
        a1 = fmaf(x1.z, h.z, a1); a1 = fmaf(x1.w, h.w, a1);
        a2 = fmaf(x2.x, h.x, a2); a2 = fmaf(x2.y, h.y, a2);
        a2 = fmaf(x2.z, h.z, a2); a2 = fmaf(x2.w, h.w, a2);
    }
    a0 += blin[js * 3 + 0]; a1 += blin[js * 3 + 1]; a2 += blin[js * 3 + 2];

    float m = fmaxf(a0, fmaxf(a1, a2));
#pragma unroll
    for (int off = 8; off; off >>= 1) m = fmaxf(m, __shfl_xor_sync(0xffffffffu, m, off, 16));
    float e0 = __expf(a0 - m), e1 = __expf(a1 - m), e2 = __expf(a2 - m);
    float s = e0 + e1 + e2;
#pragma unroll
    for (int off = 8; off; off >>= 1) s += __shfl_xor_sync(0xffffffffu, s, off, 16);
    float inv = 1.f / s;
    size_t pb = (n0 + tk) * NT + js * 3;
    g_probs[pb + 0] = e0 * inv;
    g_probs[pb + 1] = e1 * inv;
    g_probs[pb + 2] = e2 * inv;
}

// =====================================================================
// K4: CRF per batch element (unchanged)
// =====================================================================
__global__ void __launch_bounds__(64) crf_kernel(
    const int* __restrict__ labels, const int* __restrict__ seql,
    const float* __restrict__ trans, const float* __restrict__ st,
    const float* __restrict__ et)
{
    __shared__ float tr[NT * NT];
    __shared__ float alpha[NT];
    __shared__ float red[64];
    int b = blockIdx.x, tid = threadIdx.x;

    for (int i = tid; i < NT * NT; i += 64) tr[i] = trans[i];
    int L = seql[b];
    if (tid < NT) alpha[tid] = st[tid] + g_probs[(size_t)b * NS * NT + tid];
    __syncthreads();

    for (int t = 1; t < NS; ++t) {
        float na = 0.f;
        if (tid < NT) {
            float em = g_probs[((size_t)b * NS + t) * NT + tid];
            float m = -1e30f;
#pragma unroll 4
            for (int i = 0; i < NT; ++i) m = fmaxf(m, alpha[i] + tr[i * NT + tid]);
            float s = 0.f;
#pragma unroll 4
            for (int i = 0; i < NT; ++i) s += __expf(alpha[i] + tr[i * NT + tid] - m);
            na = m + __logf(s) + em;
        }
        __syncthreads();
        if (tid < NT && t < L) alpha[tid] = na;
        __syncthreads();
    }

    float loc = 0.f;
    const int* lb = labels + b * NS;
    for (int t = tid; t < NS; t += 64) {
        int tg = lb[t];
        if (t < L) {
            loc += g_probs[((size_t)b * NS + t) * NT + tg];
            if (t >= 1) loc += tr[lb[t - 1] * NT + tg];
        }
    }
    red[tid] = loc;
    __syncthreads();
    if (tid == 0) {
        float score = 0.f;
        for (int i = 0; i < 64; ++i) score += red[i];
        score += st[lb[0]] + et[lb[L - 1]];
        float m = -1e30f;
        for (int j = 0; j < NT; ++j) m = fmaxf(m, alpha[j] + et[j]);
        float s = 0.f;
        for (int j = 0; j < NT; ++j) s += __expf(alpha[j] + et[j] - m);
        float logz = m + __logf(s);
        g_res[b] = score - logz;
    }
}

__global__ void final_kernel(float* __restrict__ out) {
    if (threadIdx.x == 0) {
        float s = 0.f;
        for (int b = 0; b < NB; ++b) s += g_res[b];
        out[0] = -s;
    }
}

extern "C" void kernel_launch(void* const* d_in, const int* in_sizes, int n_in,
                              void* d_out, int out_size)
{
    (void)in_sizes; (void)n_in; (void)out_size;
    const int*   tok    = (const int*)d_in[0];
    const int*   seql   = (const int*)d_in[1];
    const int*   labels = (const int*)d_in[2];
    const float* emb    = (const float*)d_in[3];
    const float* wihf   = (const float*)d_in[4];
    const float* whhf   = (const float*)d_in[5];
    const float* bihf   = (const float*)d_in[6];
    const float* bhhf   = (const float*)d_in[7];
    const float* wihb   = (const float*)d_in[8];
    const float* whhb   = (const float*)d_in[9];
    const float* bihb   = (const float*)d_in[10];
    const float* bhhb   = (const float*)d_in[11];
    const float* wlin   = (const float*)d_in[12];
    const float* blin   = (const float*)d_in[13];
    const float* trans  = (const float*)d_in[14];
    const float* st     = (const float*)d_in[15];
    const float* et     = (const float*)d_in[16];
    float* out = (float*)d_out;

    cudaFuncSetAttribute(lstm_kernel,   cudaFuncAttributeMaxDynamicSharedMemorySize, 172032);
    cudaFuncSetAttribute(logits_kernel, cudaFuncAttributeMaxDynamicSharedMemorySize, 131840);

    dim3 g1(512, 32);
    input_gemm_kernel<<<g1, 256>>>(tok, emb, wihf, wihb, bihf, bhhf, bihb, bhhb);
    init_bar_kernel<<<1, 32>>>();
    lstm_kernel<<<128, 256, 172032>>>(whhf, whhb);
    logits_kernel<<<2048, 256, 131840>>>(wlin, blin);
    crf_kernel<<<64, 64>>>(labels, seql, trans, st, et);
    final_kernel<<<1, 32>>>(out);
}